// round 3
// baseline (speedup 1.0000x reference)
#include <cuda_runtime.h>
#include <math.h>

#define BB   32
#define EE   8
#define HW   196
#define EPS  1e-5f

#define MT       64
#define KT       16
#define NTHREADS 224
#define WD_STR   130     // dup'd W row stride (floats): 128 + 2 pad

typedef unsigned long long ull;

// ---------------- scratch (device globals; no runtime allocation) -------------
__device__ float g_pooled[BB * 1024];
__device__ float g_rw[BB * EE];
__device__ float g_cw[BB * 256 * 256 * 9];      // combined weights (max = stage 2)
__device__ float g_xcol[BB * 2304 * HW];        // im2col buffer for stage 2
__device__ float g_out1[BB * 256 * HW];
__device__ float g_out2[BB * 256 * HW];
__device__ float g_part[4 * BB * 256 * HW];     // split-K partials (4 splits)

// ---------------- f32x2 helpers -----------------------------------------------
__device__ __forceinline__ ull ffma2(ull a, ull b, ull c) {
    ull d; asm("fma.rn.f32x2 %0, %1, %2, %3;" : "=l"(d) : "l"(a), "l"(b), "l"(c));
    return d;
}
__device__ __forceinline__ ull pack2(float lo, float hi) {
    ull d; asm("mov.b64 %0, {%1,%2};" : "=l"(d) : "f"(lo), "f"(hi));
    return d;
}
__device__ __forceinline__ void unpack2(ull v, float& lo, float& hi) {
    asm("mov.b64 {%0,%1}, %2;" : "=f"(lo), "=f"(hi) : "l"(v));
}
__device__ __forceinline__ void cp16(void* smem, const void* g) {
    unsigned s = (unsigned)__cvta_generic_to_shared(smem);
    asm volatile("cp.async.cg.shared.global [%0], [%1], 16;" :: "r"(s), "l"(g));
}
#define CP_COMMIT() asm volatile("cp.async.commit_group;" ::: "memory")
#define CP_WAIT0()  asm volatile("cp.async.wait_group 0;" ::: "memory")

// ---------------- global average pool (stage-1 routing input only) ------------
__global__ void pool_kernel(const float* __restrict__ X, float* __restrict__ P, int total_rows)
{
    int warp = (blockIdx.x * blockDim.x + threadIdx.x) >> 5;
    int lane = threadIdx.x & 31;
    if (warp >= total_rows) return;
    const float* row = X + (size_t)warp * HW;
    float s = 0.f;
    for (int i = lane; i < HW; i += 32) s += row[i];
    #pragma unroll
    for (int o = 16; o; o >>= 1) s += __shfl_down_sync(0xffffffffu, s, o);
    if (lane == 0) P[warp] = s * (1.0f / HW);
}

// ---------------- routing: block per b, warp per expert -----------------------
__global__ void route_kernel(const float* __restrict__ P, const float* __restrict__ Wr,
                             const float* __restrict__ br, float* __restrict__ RW, int C)
{
    int b    = blockIdx.x;
    int e    = threadIdx.x >> 5;
    int lane = threadIdx.x & 31;
    float s = 0.f;
    for (int c = lane; c < C; c += 32) s += P[b * C + c] * Wr[c * EE + e];
    #pragma unroll
    for (int o = 16; o; o >>= 1) s += __shfl_down_sync(0xffffffffu, s, o);
    if (lane == 0) {
        float t = s + br[e];
        RW[b * EE + e] = 1.0f / (1.0f + expf(-t));
    }
}

// ---------------- expert combine: cw[b] = sum_e rw[b,e] * w[e] ---------------
__global__ void combine_kernel(const float* __restrict__ Wexp, const float* __restrict__ RW,
                               float* __restrict__ CW, int Wsz4)
{
    __shared__ float rws[BB * EE];
    if (threadIdx.x < BB * EE) rws[threadIdx.x] = RW[threadIdx.x];
    __syncthreads();
    int idx = blockIdx.x * blockDim.x + threadIdx.x;
    if (idx >= Wsz4) return;
    float4 we[EE];
    #pragma unroll
    for (int e = 0; e < EE; e++) we[e] = ((const float4*)Wexp)[(size_t)e * Wsz4 + idx];
    #pragma unroll 4
    for (int b = 0; b < BB; b++) {
        float4 acc = make_float4(0.f, 0.f, 0.f, 0.f);
        #pragma unroll
        for (int e = 0; e < EE; e++) {
            float r = rws[b * EE + e];
            acc.x = fmaf(r, we[e].x, acc.x);
            acc.y = fmaf(r, we[e].y, acc.y);
            acc.z = fmaf(r, we[e].z, acc.z);
            acc.w = fmaf(r, we[e].w, acc.w);
        }
        ((float4*)CW)[(size_t)b * Wsz4 + idx] = acc;
    }
}

// ---------------- im2col for 3x3 (pad=1): X[B,256,196] -> Xc[B,2304,196] ------
__global__ void im2col_kernel(const float* __restrict__ X, float* __restrict__ Xc, int total)
{
    int idx = blockIdx.x * blockDim.x + threadIdx.x;
    if (idx >= total) return;
    int n  = idx % HW;
    int t  = idx / HW;
    int kk = t % 2304;
    int b  = t / 2304;
    int c  = kk / 9, r = kk - 9 * c;
    int dy = r / 3 - 1, dx = r - (r / 3) * 3 - 1;
    int oy = n / 14,  ox = n - 14 * oy;
    int iy = oy + dy, ix = ox + dx;
    float v = 0.f;
    if ((unsigned)iy < 14u && (unsigned)ix < 14u)
        v = X[((size_t)b * 256 + c) * HW + iy * 14 + ix];
    Xc[idx] = v;
}

// ---------------- main GEMM: 64 x 196 block tile, f32x2, dup'd-W smem ---------
// 224 threads: mg = tid/14 (16 groups x 4 rows), ng = tid%14 (14 groups x 14 cols,
// cols packed as 7 f32x2 pairs). Inner loop per k: 4 LDS.64 (W dup) + 7 LDS.64 (X)
// + 28 FFMA2. X double-buffered via cp.async, W via LDG->reg->dup'd STS.64.
template<bool FUSE>
__global__ void __launch_bounds__(NTHREADS, 2)
gemm_kernel(const float* __restrict__ Xc, const float* __restrict__ CW,
            float* __restrict__ dst,
            const float* __restrict__ gam, const float* __restrict__ bet,
            const float* __restrict__ mu,  const float* __restrict__ var,
            const float* __restrict__ resid,
            int M_total, int K, int Kc)
{
    __shared__ __align__(16) float Xs[2][KT][HW];
    __shared__ __align__(16) float Wd[2][KT][WD_STR];

    const int b     = blockIdx.z;
    const int split = blockIdx.y;
    const int mbase = blockIdx.x * MT;
    const int tid   = threadIdx.x;
    const int mg    = tid / 14;        // 0..15
    const int ng    = tid % 14;        // 0..13
    const int n0    = 14 * ng;
    const int kbeg  = split * Kc;
    const int nk    = Kc / KT;

    const float* Xb = Xc + ((size_t)b * K + kbeg) * HW;
    const float* Wb = CW + ((size_t)b * M_total + mbase) * K + kbeg;

    ull acc[4][7];
    #pragma unroll
    for (int i = 0; i < 4; i++)
        #pragma unroll
        for (int j = 0; j < 7; j++) acc[i][j] = 0ULL;

    float wst[5];

    auto loadX = [&](int kt, int buf) {
        const float* src = Xb + (size_t)kt * KT * HW;
        #pragma unroll
        for (int i = 0; i < 4; i++) {
            int c = tid + i * NTHREADS;           // 784 16B chunks
            if (c < (KT * HW) / 4) {
                int k = c / 49, ch = c - 49 * k;
                cp16(&Xs[buf][k][ch * 4], src + (size_t)k * HW + ch * 4);
            }
        }
    };
    auto loadW_g = [&](int kt, float* wr) {
        const float* src = Wb + (size_t)kt * KT;
        #pragma unroll
        for (int i = 0; i < 5; i++) {
            int idx = tid + i * NTHREADS;
            if (idx < MT * KT) {
                int m = idx >> 4, k = idx & 15;
                wr[i] = src[(size_t)m * K + k];
            }
        }
    };
    auto storeW_dup = [&](int buf, const float* wr) {
        #pragma unroll
        for (int i = 0; i < 5; i++) {
            int idx = tid + i * NTHREADS;
            if (idx < MT * KT) {
                int m = idx >> 4, k = idx & 15;
                *(ull*)&Wd[buf][k][2 * m] = pack2(wr[i], wr[i]);
            }
        }
    };

    // ---- prologue ----
    loadX(0, 0); CP_COMMIT();
    loadW_g(0, wst);
    storeW_dup(0, wst);
    CP_WAIT0();
    __syncthreads();

    // ---- mainloop: single barrier per tile ----
    for (int kt = 0; kt < nk; kt++) {
        const int cur = kt & 1, nxt = cur ^ 1;
        const bool has = (kt + 1 < nk);
        if (has) { loadX(kt + 1, nxt); CP_COMMIT(); loadW_g(kt + 1, wst); }

        #pragma unroll
        for (int k = 0; k < KT; k++) {
            ull wv[4], xv[7];
            #pragma unroll
            for (int i = 0; i < 4; i++)
                wv[i] = *(const ull*)&Wd[cur][k][2 * (4 * mg + i)];
            #pragma unroll
            for (int j = 0; j < 7; j++)
                xv[j] = *(const ull*)&Xs[cur][k][n0 + 2 * j];
            #pragma unroll
            for (int i = 0; i < 4; i++)
                #pragma unroll
                for (int j = 0; j < 7; j++)
                    acc[i][j] = ffma2(wv[i], xv[j], acc[i][j]);
        }

        if (has) { storeW_dup(nxt, wst); CP_WAIT0(); }
        __syncthreads();
    }

    // ---- epilogue (float2 stores, n even-aligned) ----
    if (FUSE) {
        #pragma unroll
        for (int i = 0; i < 4; i++) {
            int row = mbase + 4 * mg + i;
            float inv  = rsqrtf(var[row] + EPS) * gam[row];
            float beta = bet[row] - mu[row] * inv;
            size_t base = ((size_t)b * M_total + row) * HW + n0;
            const float2* rp = (const float2*)(resid + base);
            float2*       op = (float2*)(dst + base);
            #pragma unroll
            for (int j = 0; j < 7; j++) {
                float lo, hi; unpack2(acc[i][j], lo, hi);
                float2 rv = rp[j];
                float2 v;
                v.x = fmaxf(fmaf(lo, inv, beta) + rv.x, 0.f);
                v.y = fmaxf(fmaf(hi, inv, beta) + rv.y, 0.f);
                op[j] = v;
            }
        }
    } else {
        #pragma unroll
        for (int i = 0; i < 4; i++) {
            int row = mbase + 4 * mg + i;
            size_t base = (((size_t)split * BB + b) * M_total + row) * HW + n0;
            float2* op = (float2*)(dst + base);
            #pragma unroll
            for (int j = 0; j < 7; j++) {
                float lo, hi; unpack2(acc[i][j], lo, hi);
                op[j] = make_float2(lo, hi);
            }
        }
    }
}

// ---------------- split-K(4) reduce + BN + ReLU + next-stage pool -------------
// One warp per output row (b, m). Also emits pooled means for the next router.
__global__ void reduce_bn_relu_pool(const float* __restrict__ Part, float* __restrict__ Out,
                                    float* __restrict__ Pooled,
                                    const float* __restrict__ gam, const float* __restrict__ bet,
                                    const float* __restrict__ mu,  const float* __restrict__ var,
                                    int rows)
{
    int gid  = blockIdx.x * 4 + (threadIdx.x >> 5);
    int lane = threadIdx.x & 31;
    if (gid >= rows) return;
    int m = gid & 255;
    const size_t stride = (size_t)rows * HW;
    float inv  = rsqrtf(var[m] + EPS) * gam[m];
    float beta = bet[m] - mu[m] * inv;
    size_t base = (size_t)gid * HW;
    float psum = 0.f;
    for (int n = lane; n < HW; n += 32) {
        float s = Part[base + n] + Part[stride + base + n]
                + Part[2 * stride + base + n] + Part[3 * stride + base + n];
        float v = fmaxf(fmaf(s, inv, beta), 0.f);
        Out[base + n] = v;
        psum += v;
    }
    #pragma unroll
    for (int o = 16; o; o >>= 1) psum += __shfl_down_sync(0xffffffffu, psum, o);
    if (lane == 0) Pooled[gid] = psum * (1.0f / HW);
}

// ------------------------------------------------------------------------------
extern "C" void kernel_launch(void* const* d_in, const int* in_sizes, int n_in,
                              void* d_out, int out_size)
{
    const float* x    = (const float*)d_in[0];
    const float* w1   = (const float*)d_in[1];
    const float* w2   = (const float*)d_in[2];
    const float* w3   = (const float*)d_in[3];
    const float* r1w  = (const float*)d_in[4];
    const float* r1b  = (const float*)d_in[5];
    const float* r2w  = (const float*)d_in[6];
    const float* r2b  = (const float*)d_in[7];
    const float* r3w  = (const float*)d_in[8];
    const float* r3b  = (const float*)d_in[9];
    const float* bn1g = (const float*)d_in[10];
    const float* bn1b = (const float*)d_in[11];
    const float* bn1m = (const float*)d_in[12];
    const float* bn1v = (const float*)d_in[13];
    const float* bn2g = (const float*)d_in[14];
    const float* bn2b = (const float*)d_in[15];
    const float* bn2m = (const float*)d_in[16];
    const float* bn2v = (const float*)d_in[17];
    const float* bn3g = (const float*)d_in[18];
    const float* bn3b = (const float*)d_in[19];
    const float* bn3m = (const float*)d_in[20];
    const float* bn3v = (const float*)d_in[21];
    float* out = (float*)d_out;

    float *pooled, *rw, *cw, *xcol, *o1, *o2, *part;
    cudaGetSymbolAddress((void**)&pooled, g_pooled);
    cudaGetSymbolAddress((void**)&rw,     g_rw);
    cudaGetSymbolAddress((void**)&cw,     g_cw);
    cudaGetSymbolAddress((void**)&xcol,   g_xcol);
    cudaGetSymbolAddress((void**)&o1,     g_out1);
    cudaGetSymbolAddress((void**)&o2,     g_out2);
    cudaGetSymbolAddress((void**)&part,   g_part);

    const int ROWS = BB * 256;   // 8192 output rows for stages 1/2

    // ---- stage 1: 1x1 conv, K=1024 -> M=256, split-K=4 ----
    pool_kernel<<<(BB * 1024 * 32 + 255) / 256, 256>>>(x, pooled, BB * 1024);
    route_kernel<<<BB, 256>>>(pooled, r1w, r1b, rw, 1024);
    combine_kernel<<<(256 * 1024 / 4) / 256, 256>>>(w1, rw, cw, 256 * 1024 / 4);
    gemm_kernel<false><<<dim3(256 / MT, 4, BB), NTHREADS>>>(
        x, cw, part, nullptr, nullptr, nullptr, nullptr, nullptr, 256, 1024, 256);
    reduce_bn_relu_pool<<<ROWS / 4, 128>>>(part, o1, pooled, bn1g, bn1b, bn1m, bn1v, ROWS);

    // ---- stage 2: 3x3 conv via im2col, K=2304 -> M=256, split-K=4 ----
    route_kernel<<<BB, 256>>>(pooled, r2w, r2b, rw, 256);
    combine_kernel<<<(256 * 2304 / 4) / 256, 256>>>(w2, rw, cw, 256 * 2304 / 4);
    {
        int total = BB * 2304 * HW;
        im2col_kernel<<<(total + 255) / 256, 256>>>(o1, xcol, total);
    }
    gemm_kernel<false><<<dim3(256 / MT, 4, BB), NTHREADS>>>(
        xcol, cw, part, nullptr, nullptr, nullptr, nullptr, nullptr, 256, 2304, 576);
    reduce_bn_relu_pool<<<ROWS / 4, 128>>>(part, o2, pooled, bn2g, bn2b, bn2m, bn2v, ROWS);

    // ---- stage 3: 1x1 conv, K=256 -> M=1024, fused BN+resid+ReLU ----
    route_kernel<<<BB, 256>>>(pooled, r3w, r3b, rw, 256);
    combine_kernel<<<(1024 * 256 / 4) / 256, 256>>>(w3, rw, cw, 1024 * 256 / 4);
    gemm_kernel<true><<<dim3(1024 / MT, 1, BB), NTHREADS>>>(
        o2, cw, out, bn3g, bn3b, bn3m, bn3v, x, 1024, 256, 256);
}

// round 4
// speedup vs baseline: 1.1649x; 1.1649x over previous
#include <cuda_runtime.h>
#include <math.h>

#define BB   32
#define EE   8
#define HW   196
#define EPS  1e-5f

#define MT       64
#define KT       16
#define NTHREADS 224
#define WS_STR   66    // padded row stride for Ws: conflict-free STS, 8B-aligned rows

typedef unsigned long long ull;

// ---------------- scratch (device globals; no runtime allocation) -------------
__device__ float g_pooled[BB * 1024];
__device__ float g_rw[BB * EE];
__device__ float g_cw[BB * 256 * 256 * 9];      // combined weights (max = stage 2)
__device__ float g_xcol[BB * 2304 * HW];        // im2col buffer for stage 2
__device__ float g_out1[BB * 256 * HW];
__device__ float g_out2[BB * 256 * HW];
__device__ float g_part[4 * BB * 256 * HW];     // split-K partials (4 splits)

// ---------------- f32x2 helpers -----------------------------------------------
__device__ __forceinline__ ull ffma2(ull a, ull b, ull c) {
    ull d; asm("fma.rn.f32x2 %0, %1, %2, %3;" : "=l"(d) : "l"(a), "l"(b), "l"(c));
    return d;
}
__device__ __forceinline__ ull pack2(float lo, float hi) {
    ull d; asm("mov.b64 %0, {%1,%2};" : "=l"(d) : "f"(lo), "f"(hi));
    return d;
}
__device__ __forceinline__ void unpack2(ull v, float& lo, float& hi) {
    asm("mov.b64 {%0,%1}, %2;" : "=f"(lo), "=f"(hi) : "l"(v));
}
__device__ __forceinline__ void cp16(void* smem, const void* g) {
    unsigned s = (unsigned)__cvta_generic_to_shared(smem);
    asm volatile("cp.async.cg.shared.global [%0], [%1], 16;" :: "r"(s), "l"(g));
}
#define CP_COMMIT() asm volatile("cp.async.commit_group;" ::: "memory")

// ---------------- global average pool (stage-1 routing input only) ------------
__global__ void pool_kernel(const float* __restrict__ X, float* __restrict__ P, int total_rows)
{
    int warp = (blockIdx.x * blockDim.x + threadIdx.x) >> 5;
    int lane = threadIdx.x & 31;
    if (warp >= total_rows) return;
    const float* row = X + (size_t)warp * HW;
    float s = 0.f;
    for (int i = lane; i < HW; i += 32) s += row[i];
    #pragma unroll
    for (int o = 16; o; o >>= 1) s += __shfl_down_sync(0xffffffffu, s, o);
    if (lane == 0) P[warp] = s * (1.0f / HW);
}

// ---------------- routing: block per b, warp per expert -----------------------
__global__ void route_kernel(const float* __restrict__ P, const float* __restrict__ Wr,
                             const float* __restrict__ br, float* __restrict__ RW, int C)
{
    int b    = blockIdx.x;
    int e    = threadIdx.x >> 5;
    int lane = threadIdx.x & 31;
    float s = 0.f;
    for (int c = lane; c < C; c += 32) s += P[b * C + c] * Wr[c * EE + e];
    #pragma unroll
    for (int o = 16; o; o >>= 1) s += __shfl_down_sync(0xffffffffu, s, o);
    if (lane == 0) {
        float t = s + br[e];
        RW[b * EE + e] = 1.0f / (1.0f + expf(-t));
    }
}

// ---------------- expert combine: cw[b] = sum_e rw[b,e] * w[e] ---------------
__global__ void combine_kernel(const float* __restrict__ Wexp, const float* __restrict__ RW,
                               float* __restrict__ CW, int Wsz4)
{
    __shared__ float rws[BB * EE];
    if (threadIdx.x < BB * EE) rws[threadIdx.x] = RW[threadIdx.x];
    __syncthreads();
    int idx = blockIdx.x * blockDim.x + threadIdx.x;
    if (idx >= Wsz4) return;
    float4 we[EE];
    #pragma unroll
    for (int e = 0; e < EE; e++) we[e] = ((const float4*)Wexp)[(size_t)e * Wsz4 + idx];
    #pragma unroll 4
    for (int b = 0; b < BB; b++) {
        float4 acc = make_float4(0.f, 0.f, 0.f, 0.f);
        #pragma unroll
        for (int e = 0; e < EE; e++) {
            float r = rws[b * EE + e];
            acc.x = fmaf(r, we[e].x, acc.x);
            acc.y = fmaf(r, we[e].y, acc.y);
            acc.z = fmaf(r, we[e].z, acc.z);
            acc.w = fmaf(r, we[e].w, acc.w);
        }
        ((float4*)CW)[(size_t)b * Wsz4 + idx] = acc;
    }
}

// ---------------- im2col for 3x3 (pad=1): X[B,256,196] -> Xc[B,2304,196] ------
__global__ void im2col_kernel(const float* __restrict__ X, float* __restrict__ Xc, int total)
{
    int idx = blockIdx.x * blockDim.x + threadIdx.x;
    if (idx >= total) return;
    int n  = idx % HW;
    int t  = idx / HW;
    int kk = t % 2304;
    int b  = t / 2304;
    int c  = kk / 9, r = kk - 9 * c;
    int dy = r / 3 - 1, dx = r - (r / 3) * 3 - 1;
    int oy = n / 14,  ox = n - 14 * oy;
    int iy = oy + dy, ix = ox + dx;
    float v = 0.f;
    if ((unsigned)iy < 14u && (unsigned)ix < 14u)
        v = X[((size_t)b * 256 + c) * HW + iy * 14 + ix];
    Xc[idx] = v;
}

// ---------------- main GEMM: C[b][64 x 196] tile, f32x2 FMA, double-buffered --
// (R2-proven configuration) Thread layout: my=tid/28 (8 m-groups), ny=tid%28.
// Per-thread tile: 8m (4 f32x2 pairs) x 7n, n strided by 28.
template<bool FUSE>
__global__ void __launch_bounds__(NTHREADS, 2)
gemm_kernel(const float* __restrict__ Xc, const float* __restrict__ CW,
            float* __restrict__ dst,
            const float* __restrict__ gam, const float* __restrict__ bet,
            const float* __restrict__ mu,  const float* __restrict__ var,
            const float* __restrict__ resid,
            int M_total, int K, int Kc)
{
    __shared__ __align__(16) float Xs[2][KT][HW];
    __shared__ __align__(16) float Ws[2][KT][WS_STR];

    const int b     = blockIdx.z;
    const int split = blockIdx.y;
    const int mbase = blockIdx.x * MT;
    const int tid   = threadIdx.x;
    const int my    = tid / 28;
    const int ny    = tid % 28;
    const int kbeg  = split * Kc;
    const int nk    = Kc / KT;

    const float* Xb = Xc + ((size_t)b * K + kbeg) * HW;
    const float* Wb = CW + ((size_t)b * M_total + mbase) * K + kbeg;

    ull acc[4][7];
    #pragma unroll
    for (int p = 0; p < 4; p++)
        #pragma unroll
        for (int j = 0; j < 7; j++) acc[p][j] = 0ULL;

    float wst[5];

    auto loadX = [&](int kt, int buf) {
        const float* src = Xb + (size_t)kt * KT * HW;
        #pragma unroll
        for (int i = 0; i < 4; i++) {
            int c = tid + i * NTHREADS;           // 784 chunks of 16B
            if (c < (KT * HW) / 4) {
                int k = c / 49, ch = c - 49 * k;
                cp16(&Xs[buf][k][ch * 4], src + (size_t)k * HW + ch * 4);
            }
        }
    };
    auto loadW_g = [&](int kt, float* wr) {
        const float* src = Wb + (size_t)kt * KT;
        #pragma unroll
        for (int i = 0; i < 5; i++) {
            int idx = tid + i * NTHREADS;
            if (idx < MT * KT) {
                int m = idx >> 4, k = idx & 15;
                wr[i] = src[(size_t)m * K + k];
            }
        }
    };
    auto storeW_s = [&](int buf, const float* wr) {
        #pragma unroll
        for (int i = 0; i < 5; i++) {
            int idx = tid + i * NTHREADS;
            if (idx < MT * KT) {
                int m = idx >> 4, k = idx & 15;
                Ws[buf][k][m] = wr[i];
            }
        }
    };

    // ---- pipelined mainloop (R2 structure) ----
    loadX(0, 0); CP_COMMIT();
    loadW_g(0, wst);
    storeW_s(0, wst);

    for (int kt = 0; kt < nk; kt++) {
        const int cur = kt & 1, nxt = cur ^ 1;
        const bool has = (kt + 1 < nk);
        if (has) { loadX(kt + 1, nxt); CP_COMMIT(); loadW_g(kt + 1, wst); }
        if (has) asm volatile("cp.async.wait_group 1;" ::: "memory");
        else     asm volatile("cp.async.wait_group 0;" ::: "memory");
        __syncthreads();

        #pragma unroll
        for (int k = 0; k < KT; k++) {
            ull w[4], xx[7];
            #pragma unroll
            for (int p = 0; p < 4; p++)
                w[p] = *(const ull*)&Ws[cur][k][my * 8 + 2 * p];
            #pragma unroll
            for (int j = 0; j < 7; j++) {
                float xv = Xs[cur][k][ny + 28 * j];
                xx[j] = pack2(xv, xv);
            }
            #pragma unroll
            for (int p = 0; p < 4; p++)
                #pragma unroll
                for (int j = 0; j < 7; j++)
                    acc[p][j] = ffma2(w[p], xx[j], acc[p][j]);
        }
        if (has) storeW_s(nxt, wst);
        __syncthreads();
    }

    // ---- epilogue ----
    if (FUSE) {
        #pragma unroll
        for (int p = 0; p < 4; p++) {
            int r0 = mbase + my * 8 + 2 * p;
            float i0 = rsqrtf(var[r0]     + EPS) * gam[r0];
            float b0 = bet[r0]     - mu[r0]     * i0;
            float i1 = rsqrtf(var[r0 + 1] + EPS) * gam[r0 + 1];
            float b1 = bet[r0 + 1] - mu[r0 + 1] * i1;
            size_t o0 = ((size_t)b * M_total + r0) * HW;
            #pragma unroll
            for (int j = 0; j < 7; j++) {
                float lo, hi; unpack2(acc[p][j], lo, hi);
                int n = ny + 28 * j;
                float v0 = fmaf(lo, i0, b0) + resid[o0 + n];
                float v1 = fmaf(hi, i1, b1) + resid[o0 + HW + n];
                dst[o0 + n]      = fmaxf(v0, 0.f);
                dst[o0 + HW + n] = fmaxf(v1, 0.f);
            }
        }
    } else {
        #pragma unroll
        for (int p = 0; p < 4; p++) {
            int r0 = mbase + my * 8 + 2 * p;
            size_t o0 = (((size_t)split * BB + b) * M_total + r0) * HW;
            #pragma unroll
            for (int j = 0; j < 7; j++) {
                float lo, hi; unpack2(acc[p][j], lo, hi);
                int n = ny + 28 * j;
                dst[o0 + n]      = lo;
                dst[o0 + HW + n] = hi;
            }
        }
    }
}

// ---------------- split-K(4) reduce + BN + ReLU + next-stage pool -------------
// One warp per output row (b, m). Also emits pooled means for the next router.
__global__ void reduce_bn_relu_pool(const float* __restrict__ Part, float* __restrict__ Out,
                                    float* __restrict__ Pooled,
                                    const float* __restrict__ gam, const float* __restrict__ bet,
                                    const float* __restrict__ mu,  const float* __restrict__ var,
                                    int rows)
{
    int gid  = blockIdx.x * 4 + (threadIdx.x >> 5);
    int lane = threadIdx.x & 31;
    if (gid >= rows) return;
    int m = gid & 255;
    const size_t stride = (size_t)rows * HW;
    float inv  = rsqrtf(var[m] + EPS) * gam[m];
    float beta = bet[m] - mu[m] * inv;
    size_t base = (size_t)gid * HW;
    float psum = 0.f;
    for (int n = lane; n < HW; n += 32) {
        float s = Part[base + n] + Part[stride + base + n]
                + Part[2 * stride + base + n] + Part[3 * stride + base + n];
        float v = fmaxf(fmaf(s, inv, beta), 0.f);
        Out[base + n] = v;
        psum += v;
    }
    #pragma unroll
    for (int o = 16; o; o >>= 1) psum += __shfl_down_sync(0xffffffffu, psum, o);
    if (lane == 0) Pooled[gid] = psum * (1.0f / HW);
}

// ------------------------------------------------------------------------------
extern "C" void kernel_launch(void* const* d_in, const int* in_sizes, int n_in,
                              void* d_out, int out_size)
{
    const float* x    = (const float*)d_in[0];
    const float* w1   = (const float*)d_in[1];
    const float* w2   = (const float*)d_in[2];
    const float* w3   = (const float*)d_in[3];
    const float* r1w  = (const float*)d_in[4];
    const float* r1b  = (const float*)d_in[5];
    const float* r2w  = (const float*)d_in[6];
    const float* r2b  = (const float*)d_in[7];
    const float* r3w  = (const float*)d_in[8];
    const float* r3b  = (const float*)d_in[9];
    const float* bn1g = (const float*)d_in[10];
    const float* bn1b = (const float*)d_in[11];
    const float* bn1m = (const float*)d_in[12];
    const float* bn1v = (const float*)d_in[13];
    const float* bn2g = (const float*)d_in[14];
    const float* bn2b = (const float*)d_in[15];
    const float* bn2m = (const float*)d_in[16];
    const float* bn2v = (const float*)d_in[17];
    const float* bn3g = (const float*)d_in[18];
    const float* bn3b = (const float*)d_in[19];
    const float* bn3m = (const float*)d_in[20];
    const float* bn3v = (const float*)d_in[21];
    float* out = (float*)d_out;

    float *pooled, *rw, *cw, *xcol, *o1, *o2, *part;
    cudaGetSymbolAddress((void**)&pooled, g_pooled);
    cudaGetSymbolAddress((void**)&rw,     g_rw);
    cudaGetSymbolAddress((void**)&cw,     g_cw);
    cudaGetSymbolAddress((void**)&xcol,   g_xcol);
    cudaGetSymbolAddress((void**)&o1,     g_out1);
    cudaGetSymbolAddress((void**)&o2,     g_out2);
    cudaGetSymbolAddress((void**)&part,   g_part);

    const int ROWS = BB * 256;   // 8192 output rows for stages 1/2

    // ---- stage 1: 1x1 conv, K=1024 -> M=256, split-K=4 ----
    pool_kernel<<<(BB * 1024 * 32 + 255) / 256, 256>>>(x, pooled, BB * 1024);
    route_kernel<<<BB, 256>>>(pooled, r1w, r1b, rw, 1024);
    combine_kernel<<<(256 * 1024 / 4) / 256, 256>>>(w1, rw, cw, 256 * 1024 / 4);
    gemm_kernel<false><<<dim3(256 / MT, 4, BB), NTHREADS>>>(
        x, cw, part, nullptr, nullptr, nullptr, nullptr, nullptr, 256, 1024, 256);
    reduce_bn_relu_pool<<<ROWS / 4, 128>>>(part, o1, pooled, bn1g, bn1b, bn1m, bn1v, ROWS);

    // ---- stage 2: 3x3 conv via im2col, K=2304 -> M=256, split-K=4 ----
    route_kernel<<<BB, 256>>>(pooled, r2w, r2b, rw, 256);
    combine_kernel<<<(256 * 2304 / 4) / 256, 256>>>(w2, rw, cw, 256 * 2304 / 4);
    {
        int total = BB * 2304 * HW;
        im2col_kernel<<<(total + 255) / 256, 256>>>(o1, xcol, total);
    }
    gemm_kernel<false><<<dim3(256 / MT, 4, BB), NTHREADS>>>(
        xcol, cw, part, nullptr, nullptr, nullptr, nullptr, nullptr, 256, 2304, 576);
    reduce_bn_relu_pool<<<ROWS / 4, 128>>>(part, o2, pooled, bn2g, bn2b, bn2m, bn2v, ROWS);

    // ---- stage 3: 1x1 conv, K=256 -> M=1024, fused BN+resid+ReLU ----
    route_kernel<<<BB, 256>>>(pooled, r3w, r3b, rw, 256);
    combine_kernel<<<(1024 * 256 / 4) / 256, 256>>>(w3, rw, cw, 1024 * 256 / 4);
    gemm_kernel<true><<<dim3(1024 / MT, 1, BB), NTHREADS>>>(
        o2, cw, out, bn3g, bn3b, bn3m, bn3v, x, 1024, 256, 256);
}

// round 5
// speedup vs baseline: 1.2236x; 1.0504x over previous
#include <cuda_runtime.h>
#include <math.h>

#define BB   32
#define EE   8
#define HW   196
#define EPS  1e-5f

#define MT       64
#define KT       16
#define NTHREADS 224
#define WS_STR   66    // padded Ws row stride: conflict-free STS, 8B-aligned rows
#define XS_STR   260   // padded 16x16 halo tile + 4

typedef unsigned long long ull;

// ---------------- scratch (device globals; no runtime allocation) -------------
__device__ float g_pooled[BB * 1024];
__device__ float g_rw[BB * EE];
__device__ float g_cw[BB * 256 * 256 * 9];      // combined weights (max = stage 2)
__device__ float g_out1[BB * 256 * HW];
__device__ float g_out2[BB * 256 * HW];
__device__ float g_part[2 * BB * 256 * HW];     // split-K partials (2 splits)

// ---------------- f32x2 helpers -----------------------------------------------
__device__ __forceinline__ ull ffma2(ull a, ull b, ull c) {
    ull d; asm("fma.rn.f32x2 %0, %1, %2, %3;" : "=l"(d) : "l"(a), "l"(b), "l"(c));
    return d;
}
__device__ __forceinline__ ull pack2(float lo, float hi) {
    ull d; asm("mov.b64 %0, {%1,%2};" : "=l"(d) : "f"(lo), "f"(hi));
    return d;
}
__device__ __forceinline__ void unpack2(ull v, float& lo, float& hi) {
    asm("mov.b64 {%0,%1}, %2;" : "=f"(lo), "=f"(hi) : "l"(v));
}
__device__ __forceinline__ void cp16(void* smem, const void* g) {
    unsigned s = (unsigned)__cvta_generic_to_shared(smem);
    asm volatile("cp.async.cg.shared.global [%0], [%1], 16;" :: "r"(s), "l"(g));
}
#define CP_COMMIT() asm volatile("cp.async.commit_group;" ::: "memory")

// ---------------- global average pool (stage-1 routing input only) ------------
__global__ void pool_kernel(const float* __restrict__ X, float* __restrict__ P, int total_rows)
{
    int warp = (blockIdx.x * blockDim.x + threadIdx.x) >> 5;
    int lane = threadIdx.x & 31;
    if (warp >= total_rows) return;
    const float* row = X + (size_t)warp * HW;
    float s = 0.f;
    for (int i = lane; i < HW; i += 32) s += row[i];
    #pragma unroll
    for (int o = 16; o; o >>= 1) s += __shfl_down_sync(0xffffffffu, s, o);
    if (lane == 0) P[warp] = s * (1.0f / HW);
}

// ---------------- routing: block per b, warp per expert -----------------------
__global__ void route_kernel(const float* __restrict__ P, const float* __restrict__ Wr,
                             const float* __restrict__ br, float* __restrict__ RW, int C)
{
    int b    = blockIdx.x;
    int e    = threadIdx.x >> 5;
    int lane = threadIdx.x & 31;
    float s = 0.f;
    for (int c = lane; c < C; c += 32) s += P[b * C + c] * Wr[c * EE + e];
    #pragma unroll
    for (int o = 16; o; o >>= 1) s += __shfl_down_sync(0xffffffffu, s, o);
    if (lane == 0) {
        float t = s + br[e];
        RW[b * EE + e] = 1.0f / (1.0f + expf(-t));
    }
}

// ---------------- expert combine: cw[b] = sum_e rw[b,e] * w[e] ---------------
__global__ void combine_kernel(const float* __restrict__ Wexp, const float* __restrict__ RW,
                               float* __restrict__ CW, int Wsz4)
{
    __shared__ float rws[BB * EE];
    if (threadIdx.x < BB * EE) rws[threadIdx.x] = RW[threadIdx.x];
    __syncthreads();
    int idx = blockIdx.x * blockDim.x + threadIdx.x;
    if (idx >= Wsz4) return;
    float4 we[EE];
    #pragma unroll
    for (int e = 0; e < EE; e++) we[e] = ((const float4*)Wexp)[(size_t)e * Wsz4 + idx];
    #pragma unroll 4
    for (int b = 0; b < BB; b++) {
        float4 acc = make_float4(0.f, 0.f, 0.f, 0.f);
        #pragma unroll
        for (int e = 0; e < EE; e++) {
            float r = rws[b * EE + e];
            acc.x = fmaf(r, we[e].x, acc.x);
            acc.y = fmaf(r, we[e].y, acc.y);
            acc.z = fmaf(r, we[e].z, acc.z);
            acc.w = fmaf(r, we[e].w, acc.w);
        }
        ((float4*)CW)[(size_t)b * Wsz4 + idx] = acc;
    }
}

// ---------------- 1x1 GEMM (R2-proven loop): 64 x 196 tile, f32x2 -------------
template<bool FUSE>
__global__ void __launch_bounds__(NTHREADS, 2)
gemm_kernel(const float* __restrict__ Xc, const float* __restrict__ CW,
            float* __restrict__ dst,
            const float* __restrict__ gam, const float* __restrict__ bet,
            const float* __restrict__ mu,  const float* __restrict__ var,
            const float* __restrict__ resid,
            int M_total, int K, int Kc)
{
    __shared__ __align__(16) float Xs[2][KT][HW];
    __shared__ __align__(16) float Ws[2][KT][WS_STR];

    const int b     = blockIdx.z;
    const int split = blockIdx.y;
    const int mbase = blockIdx.x * MT;
    const int tid   = threadIdx.x;
    const int my    = tid / 28;
    const int ny    = tid % 28;
    const int kbeg  = split * Kc;
    const int nk    = Kc / KT;

    const float* Xb = Xc + ((size_t)b * K + kbeg) * HW;
    const float* Wb = CW + ((size_t)b * M_total + mbase) * K + kbeg;

    ull acc[4][7];
    #pragma unroll
    for (int p = 0; p < 4; p++)
        #pragma unroll
        for (int j = 0; j < 7; j++) acc[p][j] = 0ULL;

    float wst[5];

    auto loadX = [&](int kt, int buf) {
        const float* src = Xb + (size_t)kt * KT * HW;
        #pragma unroll
        for (int i = 0; i < 4; i++) {
            int c = tid + i * NTHREADS;
            if (c < (KT * HW) / 4) {
                int k = c / 49, ch = c - 49 * k;
                cp16(&Xs[buf][k][ch * 4], src + (size_t)k * HW + ch * 4);
            }
        }
    };
    auto loadW_g = [&](int kt, float* wr) {
        const float* src = Wb + (size_t)kt * KT;
        #pragma unroll
        for (int i = 0; i < 5; i++) {
            int idx = tid + i * NTHREADS;
            if (idx < MT * KT) {
                int m = idx >> 4, k = idx & 15;
                wr[i] = src[(size_t)m * K + k];
            }
        }
    };
    auto storeW_s = [&](int buf, const float* wr) {
        #pragma unroll
        for (int i = 0; i < 5; i++) {
            int idx = tid + i * NTHREADS;
            if (idx < MT * KT) {
                int m = idx >> 4, k = idx & 15;
                Ws[buf][k][m] = wr[i];
            }
        }
    };

    loadX(0, 0); CP_COMMIT();
    loadW_g(0, wst);
    storeW_s(0, wst);

    for (int kt = 0; kt < nk; kt++) {
        const int cur = kt & 1, nxt = cur ^ 1;
        const bool has = (kt + 1 < nk);
        if (has) { loadX(kt + 1, nxt); CP_COMMIT(); loadW_g(kt + 1, wst); }
        if (has) asm volatile("cp.async.wait_group 1;" ::: "memory");
        else     asm volatile("cp.async.wait_group 0;" ::: "memory");
        __syncthreads();

        #pragma unroll
        for (int k = 0; k < KT; k++) {
            ull w[4], xx[7];
            #pragma unroll
            for (int p = 0; p < 4; p++)
                w[p] = *(const ull*)&Ws[cur][k][my * 8 + 2 * p];
            #pragma unroll
            for (int j = 0; j < 7; j++) {
                float xv = Xs[cur][k][ny + 28 * j];
                xx[j] = pack2(xv, xv);
            }
            #pragma unroll
            for (int p = 0; p < 4; p++)
                #pragma unroll
                for (int j = 0; j < 7; j++)
                    acc[p][j] = ffma2(w[p], xx[j], acc[p][j]);
        }
        if (has) storeW_s(nxt, wst);
        __syncthreads();
    }

    if (FUSE) {
        #pragma unroll
        for (int p = 0; p < 4; p++) {
            int r0 = mbase + my * 8 + 2 * p;
            float i0 = rsqrtf(var[r0]     + EPS) * gam[r0];
            float b0 = bet[r0]     - mu[r0]     * i0;
            float i1 = rsqrtf(var[r0 + 1] + EPS) * gam[r0 + 1];
            float b1 = bet[r0 + 1] - mu[r0 + 1] * i1;
            size_t o0 = ((size_t)b * M_total + r0) * HW;
            #pragma unroll
            for (int j = 0; j < 7; j++) {
                float lo, hi; unpack2(acc[p][j], lo, hi);
                int n = ny + 28 * j;
                float v0 = fmaf(lo, i0, b0) + resid[o0 + n];
                float v1 = fmaf(hi, i1, b1) + resid[o0 + HW + n];
                dst[o0 + n]      = fmaxf(v0, 0.f);
                dst[o0 + HW + n] = fmaxf(v1, 0.f);
            }
        }
    } else {
        #pragma unroll
        for (int p = 0; p < 4; p++) {
            int r0 = mbase + my * 8 + 2 * p;
            size_t o0 = (((size_t)split * BB + b) * M_total + r0) * HW;
            #pragma unroll
            for (int j = 0; j < 7; j++) {
                float lo, hi; unpack2(acc[p][j], lo, hi);
                int n = ny + 28 * j;
                dst[o0 + n]      = lo;
                dst[o0 + HW + n] = hi;
            }
        }
    }
}

// ---------------- stage-2 3x3 conv GEMM: halo-padded X reuse over 9 taps ------
// X tile: 16 channels in padded 16x16 halo layout (zero border), loaded ONCE per
// channel tile; 9 taps read it with smem-offset shift dy*16+dx. W streamed per
// (channel-tile, tap) exactly like the proven 1x1 W path. Inner loop identical
// to gemm_kernel. Split-K over channels (2 x 128). K_full = 2304, k = c*9 + r.
__global__ void __launch_bounds__(NTHREADS, 2)
conv3_kernel(const float* __restrict__ X, const float* __restrict__ CW,
             float* __restrict__ Part)
{
    __shared__ __align__(16) float Xs[2][KT][XS_STR];
    __shared__ __align__(16) float Ws[2][KT][WS_STR];

    const int b     = blockIdx.z;
    const int split = blockIdx.y;
    const int mbase = blockIdx.x * MT;
    const int tid   = threadIdx.x;
    const int my    = tid / 28;
    const int ny    = tid % 28;
    const int c0    = split * 128;          // absolute channel base
    const int nct   = 128 / KT;             // 8 channel tiles

    const float* Xb = X + (size_t)b * 256 * HW;
    const float* Wb = CW + ((size_t)b * 256 + mbase) * 2304;

    // per-thread padded smem offsets for 7 output columns
    int off[7];
    #pragma unroll
    for (int j = 0; j < 7; j++) {
        int n = ny + 28 * j;
        off[j] = (n / 14 + 1) * 16 + (n % 14) + 1;
    }

    ull acc[4][7];
    #pragma unroll
    for (int p = 0; p < 4; p++)
        #pragma unroll
        for (int j = 0; j < 7; j++) acc[p][j] = 0ULL;

    auto loadX_g = [&](int ct, float* xr) {
        const float* src = Xb + (size_t)(c0 + ct * KT) * HW;
        #pragma unroll
        for (int i = 0; i < 14; i++) {
            int idx = tid + i * NTHREADS;        // 3136 = 14*224 exactly
            int c = idx / HW, n = idx - c * HW;
            xr[i] = src[(size_t)c * HW + n];
        }
    };
    auto storeX_s = [&](int buf, const float* xr) {
        #pragma unroll
        for (int i = 0; i < 14; i++) {
            int idx = tid + i * NTHREADS;
            int c = idx / HW, n = idx - c * HW;
            int iy = n / 14, ix = n - 14 * iy;
            Xs[buf][c][(iy + 1) * 16 + ix + 1] = xr[i];
        }
    };
    auto loadW_g = [&](int ct, int r, float* wr) {
        #pragma unroll
        for (int i = 0; i < 5; i++) {
            int idx = tid + i * NTHREADS;
            if (idx < MT * KT) {
                int m = idx >> 4, kl = idx & 15;
                wr[i] = Wb[(size_t)m * 2304 + (c0 + ct * KT + kl) * 9 + r];
            }
        }
    };
    auto storeW_s = [&](int buf, const float* wr) {
        #pragma unroll
        for (int i = 0; i < 5; i++) {
            int idx = tid + i * NTHREADS;
            if (idx < MT * KT) {
                int m = idx >> 4, kl = idx & 15;
                Ws[buf][kl][m] = wr[i];
            }
        }
    };

    // zero both X buffers (halo cells stay zero forever)
    for (int i = tid; i < 2 * KT * XS_STR; i += NTHREADS)
        ((float*)Xs)[i] = 0.f;
    __syncthreads();

    // prologue
    {
        float xr[14];
        loadX_g(0, xr);
        storeX_s(0, xr);
        float wst[5];
        loadW_g(0, 0, wst);
        storeW_s(0, wst);
    }
    __syncthreads();

    int wb = 0;
    for (int ct = 0; ct < nct; ct++) {
        const int  xb    = ct & 1;
        const bool havex = (ct + 1 < nct);
        float xst[14];
        for (int r = 0; r < 9; r++) {
            const bool haven = (r < 8) || havex;
            float wnx[5];
            if (haven) {
                int nc = (r < 8) ? ct : ct + 1;
                int nr = (r < 8) ? r + 1 : 0;
                loadW_g(nc, nr, wnx);
            }
            if (r == 0 && havex) loadX_g(ct + 1, xst);

            const int sh = (r / 3 - 1) * 16 + (r - (r / 3) * 3 - 1);
            #pragma unroll
            for (int k = 0; k < KT; k++) {
                ull w[4], xx[7];
                #pragma unroll
                for (int p = 0; p < 4; p++)
                    w[p] = *(const ull*)&Ws[wb][k][my * 8 + 2 * p];
                #pragma unroll
                for (int j = 0; j < 7; j++) {
                    float xv = Xs[xb][k][off[j] + sh];
                    xx[j] = pack2(xv, xv);
                }
                #pragma unroll
                for (int p = 0; p < 4; p++)
                    #pragma unroll
                    for (int j = 0; j < 7; j++)
                        acc[p][j] = ffma2(w[p], xx[j], acc[p][j]);
            }

            if (r == 1 && havex) storeX_s(xb ^ 1, xst);
            if (haven) storeW_s(wb ^ 1, wnx);
            __syncthreads();
            wb ^= 1;
        }
    }

    // epilogue: split-K partial store
    #pragma unroll
    for (int p = 0; p < 4; p++) {
        int r0 = mbase + my * 8 + 2 * p;
        size_t o0 = (((size_t)split * BB + b) * 256 + r0) * HW;
        #pragma unroll
        for (int j = 0; j < 7; j++) {
            float lo, hi; unpack2(acc[p][j], lo, hi);
            int n = ny + 28 * j;
            Part[o0 + n]      = lo;
            Part[o0 + HW + n] = hi;
        }
    }
}

// ---------------- split-K(2) reduce + BN + ReLU + next-stage pool -------------
__global__ void reduce_bn_relu_pool(const float* __restrict__ Part, float* __restrict__ Out,
                                    float* __restrict__ Pooled,
                                    const float* __restrict__ gam, const float* __restrict__ bet,
                                    const float* __restrict__ mu,  const float* __restrict__ var,
                                    int rows)
{
    int gid  = blockIdx.x * 4 + (threadIdx.x >> 5);
    int lane = threadIdx.x & 31;
    if (gid >= rows) return;
    int m = gid & 255;
    const size_t stride = (size_t)rows * HW;
    float inv  = rsqrtf(var[m] + EPS) * gam[m];
    float beta = bet[m] - mu[m] * inv;
    size_t base = (size_t)gid * HW;
    float psum = 0.f;
    for (int n = lane; n < HW; n += 32) {
        float s = Part[base + n] + Part[stride + base + n];
        float v = fmaxf(fmaf(s, inv, beta), 0.f);
        Out[base + n] = v;
        psum += v;
    }
    #pragma unroll
    for (int o = 16; o; o >>= 1) psum += __shfl_down_sync(0xffffffffu, psum, o);
    if (lane == 0) Pooled[gid] = psum * (1.0f / HW);
}

// ------------------------------------------------------------------------------
extern "C" void kernel_launch(void* const* d_in, const int* in_sizes, int n_in,
                              void* d_out, int out_size)
{
    const float* x    = (const float*)d_in[0];
    const float* w1   = (const float*)d_in[1];
    const float* w2   = (const float*)d_in[2];
    const float* w3   = (const float*)d_in[3];
    const float* r1w  = (const float*)d_in[4];
    const float* r1b  = (const float*)d_in[5];
    const float* r2w  = (const float*)d_in[6];
    const float* r2b  = (const float*)d_in[7];
    const float* r3w  = (const float*)d_in[8];
    const float* r3b  = (const float*)d_in[9];
    const float* bn1g = (const float*)d_in[10];
    const float* bn1b = (const float*)d_in[11];
    const float* bn1m = (const float*)d_in[12];
    const float* bn1v = (const float*)d_in[13];
    const float* bn2g = (const float*)d_in[14];
    const float* bn2b = (const float*)d_in[15];
    const float* bn2m = (const float*)d_in[16];
    const float* bn2v = (const float*)d_in[17];
    const float* bn3g = (const float*)d_in[18];
    const float* bn3b = (const float*)d_in[19];
    const float* bn3m = (const float*)d_in[20];
    const float* bn3v = (const float*)d_in[21];
    float* out = (float*)d_out;

    float *pooled, *rw, *cw, *o1, *o2, *part;
    cudaGetSymbolAddress((void**)&pooled, g_pooled);
    cudaGetSymbolAddress((void**)&rw,     g_rw);
    cudaGetSymbolAddress((void**)&cw,     g_cw);
    cudaGetSymbolAddress((void**)&o1,     g_out1);
    cudaGetSymbolAddress((void**)&o2,     g_out2);
    cudaGetSymbolAddress((void**)&part,   g_part);

    const int ROWS = BB * 256;   // 8192 output rows for stages 1/2

    // ---- stage 1: 1x1 conv, K=1024 -> M=256, split-K=2 ----
    pool_kernel<<<(BB * 1024 * 32 + 255) / 256, 256>>>(x, pooled, BB * 1024);
    route_kernel<<<BB, 256>>>(pooled, r1w, r1b, rw, 1024);
    combine_kernel<<<(256 * 1024 / 4) / 256, 256>>>(w1, rw, cw, 256 * 1024 / 4);
    gemm_kernel<false><<<dim3(256 / MT, 2, BB), NTHREADS>>>(
        x, cw, part, nullptr, nullptr, nullptr, nullptr, nullptr, 256, 1024, 512);
    reduce_bn_relu_pool<<<ROWS / 4, 128>>>(part, o1, pooled, bn1g, bn1b, bn1m, bn1v, ROWS);

    // ---- stage 2: 3x3 conv (halo-shift), K=256ch x 9 -> M=256, split-K=2 ----
    route_kernel<<<BB, 256>>>(pooled, r2w, r2b, rw, 256);
    combine_kernel<<<(256 * 2304 / 4) / 256, 256>>>(w2, rw, cw, 256 * 2304 / 4);
    conv3_kernel<<<dim3(256 / MT, 2, BB), NTHREADS>>>(o1, cw, part);
    reduce_bn_relu_pool<<<ROWS / 4, 128>>>(part, o2, pooled, bn2g, bn2b, bn2m, bn2v, ROWS);

    // ---- stage 3: 1x1 conv, K=256 -> M=1024, fused BN+resid+ReLU ----
    route_kernel<<<BB, 256>>>(pooled, r3w, r3b, rw, 256);
    combine_kernel<<<(1024 * 256 / 4) / 256, 256>>>(w3, rw, cw, 1024 * 256 / 4);
    gemm_kernel<true><<<dim3(1024 / MT, 1, BB), NTHREADS>>>(
        o2, cw, out, bn3g, bn3b, bn3m, bn3v, x, 1024, 256, 256);
}

// round 7
// speedup vs baseline: 1.6460x; 1.3452x over previous
#include <cuda_runtime.h>
#include <cuda_bf16.h>
#include <math.h>
#include <stdint.h>

#define BB   32
#define EE   8
#define HW   196
#define NP   224          // padded N (196 -> 224)
#define EPS  1e-5f

typedef unsigned long long ull;
typedef __nv_bfloat16 bf16;

// ---------------- scratch (device globals; no runtime allocation) -------------
__device__ float g_pooled[BB * 1024];
__device__ float g_rw[BB * EE];
__device__ float g_o1[BB * 256 * HW];
__device__ float g_o2[BB * 256 * HW];
__device__ float g_part[2 * BB * 256 * HW];
__device__ bf16  g_cwh[BB * 256 * 2304];
__device__ bf16  g_cwl[BB * 256 * 2304];
__device__ bf16  g_xth[BB * NP * 2304];
__device__ bf16  g_xtl[BB * NP * 2304];

// ---------------- helpers -------------------------------------------------------
__device__ __forceinline__ void cp16(void* s, const void* g) {
    unsigned a = (unsigned)__cvta_generic_to_shared(s);
    asm volatile("cp.async.cg.shared.global [%0], [%1], 16;" :: "r"(a), "l"(g));
}
#define CP_COMMIT() asm volatile("cp.async.commit_group;" ::: "memory")

__device__ __forceinline__ uint32_t smem_u32(const void* p) {
    return (uint32_t)__cvta_generic_to_shared(p);
}
__device__ __forceinline__ void ldsm_x4(uint32_t* r, uint32_t a) {
    asm volatile("ldmatrix.sync.aligned.m8n8.x4.shared.b16 {%0,%1,%2,%3}, [%4];"
                 : "=r"(r[0]), "=r"(r[1]), "=r"(r[2]), "=r"(r[3]) : "r"(a));
}
__device__ __forceinline__ void ldsm_x2(uint32_t* r, uint32_t a) {
    asm volatile("ldmatrix.sync.aligned.m8n8.x2.shared.b16 {%0,%1}, [%2];"
                 : "=r"(r[0]), "=r"(r[1]) : "r"(a));
}
__device__ __forceinline__ void mma_bf16(float* d, const uint32_t* a, const uint32_t* b) {
    asm volatile("mma.sync.aligned.m16n8k16.row.col.f32.bf16.bf16.f32 "
                 "{%0,%1,%2,%3}, {%4,%5,%6,%7}, {%8,%9}, {%0,%1,%2,%3};"
                 : "+f"(d[0]), "+f"(d[1]), "+f"(d[2]), "+f"(d[3])
                 : "r"(a[0]), "r"(a[1]), "r"(a[2]), "r"(a[3]), "r"(b[0]), "r"(b[1]));
}

// ---------------- pool / route --------------------------------------------------
__global__ void pool_kernel(const float* __restrict__ X, float* __restrict__ P, int total_rows)
{
    int warp = (blockIdx.x * blockDim.x + threadIdx.x) >> 5;
    int lane = threadIdx.x & 31;
    if (warp >= total_rows) return;
    const float* row = X + (size_t)warp * HW;
    float s = 0.f;
    for (int i = lane; i < HW; i += 32) s += row[i];
    #pragma unroll
    for (int o = 16; o; o >>= 1) s += __shfl_down_sync(0xffffffffu, s, o);
    if (lane == 0) P[warp] = s * (1.0f / HW);
}

__global__ void route_kernel(const float* __restrict__ P, const float* __restrict__ Wr,
                             const float* __restrict__ br, float* __restrict__ RW, int C)
{
    int b = blockIdx.x, e = threadIdx.x >> 5, lane = threadIdx.x & 31;
    float s = 0.f;
    for (int c = lane; c < C; c += 32) s += P[b * C + c] * Wr[c * EE + e];
    #pragma unroll
    for (int o = 16; o; o >>= 1) s += __shfl_down_sync(0xffffffffu, s, o);
    if (lane == 0) RW[b * EE + e] = 1.0f / (1.0f + expf(-(s + br[e])));
}

// ---------------- combine (K-major) -> bf16 hi/lo -------------------------------
__global__ void combine_bf16_kernel(const float* __restrict__ Wexp, const float* __restrict__ RW,
                                    bf16* __restrict__ CWh, bf16* __restrict__ CWl, int Wsz)
{
    __shared__ float rws[BB * EE];
    if (threadIdx.x < BB * EE) rws[threadIdx.x] = RW[threadIdx.x];
    __syncthreads();
    int idx = blockIdx.x * blockDim.x + threadIdx.x;
    if (idx >= Wsz / 4) return;
    float4 we[EE];
    #pragma unroll
    for (int e = 0; e < EE; e++) we[e] = ((const float4*)Wexp)[(size_t)e * (Wsz / 4) + idx];
    #pragma unroll 4
    for (int b = 0; b < BB; b++) {
        float4 a = make_float4(0.f, 0.f, 0.f, 0.f);
        #pragma unroll
        for (int e = 0; e < EE; e++) {
            float r = rws[b * EE + e];
            a.x = fmaf(r, we[e].x, a.x); a.y = fmaf(r, we[e].y, a.y);
            a.z = fmaf(r, we[e].z, a.z); a.w = fmaf(r, we[e].w, a.w);
        }
        bf16 h0 = __float2bfloat16(a.x), h1 = __float2bfloat16(a.y);
        bf16 h2 = __float2bfloat16(a.z), h3 = __float2bfloat16(a.w);
        float l0 = a.x - __bfloat162float(h0), l1 = a.y - __bfloat162float(h1);
        float l2 = a.z - __bfloat162float(h2), l3 = a.w - __bfloat162float(h3);
        size_t o = (size_t)b * Wsz + (size_t)idx * 4;
        CWh[o] = h0; CWh[o + 1] = h1; CWh[o + 2] = h2; CWh[o + 3] = h3;
        CWl[o] = __float2bfloat16(l0); CWl[o + 1] = __float2bfloat16(l1);
        CWl[o + 2] = __float2bfloat16(l2); CWl[o + 3] = __float2bfloat16(l3);
    }
}

// ---------------- combine for stage 2: k = r*256 + c ----------------------------
__global__ void combine2_kernel(const float* __restrict__ W2, const float* __restrict__ RW,
                                bf16* __restrict__ CWh, bf16* __restrict__ CWl)
{
    __shared__ float rws[BB * EE];
    if (threadIdx.x < BB * EE) rws[threadIdx.x] = RW[threadIdx.x];
    __syncthreads();
    int m = blockIdx.x, c = threadIdx.x;
    float w[EE][9];
    #pragma unroll
    for (int e = 0; e < EE; e++)
        #pragma unroll
        for (int r = 0; r < 9; r++)
            w[e][r] = W2[((size_t)e * 256 * 256 + m * 256 + c) * 9 + r];
    for (int b = 0; b < BB; b++) {
        float acc[9];
        #pragma unroll
        for (int r = 0; r < 9; r++) acc[r] = 0.f;
        #pragma unroll
        for (int e = 0; e < EE; e++) {
            float rv = rws[b * EE + e];
            #pragma unroll
            for (int r = 0; r < 9; r++) acc[r] = fmaf(rv, w[e][r], acc[r]);
        }
        size_t base = ((size_t)b * 256 + m) * 2304 + c;
        #pragma unroll
        for (int r = 0; r < 9; r++) {
            bf16 h = __float2bfloat16(acc[r]);
            float l = acc[r] - __bfloat162float(h);
            CWh[base + r * 256] = h;
            CWl[base + r * 256] = __float2bfloat16(l);
        }
    }
}

// ---------------- transpose-convert: src[b][K][196] f32 -> dst[b][224][K] bf16 --
__global__ void transpose_kernel(const float* __restrict__ src,
                                 bf16* __restrict__ dhi, bf16* __restrict__ dlo, int K)
{
    __shared__ float t[32][33];
    int b = blockIdx.z, k0 = blockIdx.x * 32, n0 = blockIdx.y * 32;
    int tx = threadIdx.x, ty = threadIdx.y;
    const float* s = src + (size_t)b * K * HW;
    #pragma unroll
    for (int i = 0; i < 4; i++) {
        int kl = ty + 8 * i, n = n0 + tx;
        t[kl][tx] = (n < HW) ? s[(size_t)(k0 + kl) * HW + n] : 0.f;
    }
    __syncthreads();
    #pragma unroll
    for (int i = 0; i < 4; i++) {
        int nl = ty + 8 * i;
        float v = t[tx][nl];
        bf16 h = __float2bfloat16(v);
        float l = v - __bfloat162float(h);
        size_t o = ((size_t)b * NP + (n0 + nl)) * K + k0 + tx;
        dhi[o] = h;
        dlo[o] = __float2bfloat16(l);
    }
}

// ---------------- stage-2 im2col-transpose: o1[b][256][196] -> xt[b][224][2304] -
__global__ void __launch_bounds__(256)
xt2_kernel(const float* __restrict__ o1, bf16* __restrict__ dhi, bf16* __restrict__ dlo)
{
    __shared__ float sm[128][57];
    const int ng = blockIdx.x, c0 = blockIdx.y * 128, b = blockIdx.z;
    const int tid = threadIdx.x, lane = tid & 31, wrp = tid >> 5;
    const int n0 = ng * 16;
    const int wy0 = n0 / 14 - 1;

    const float* src = o1 + ((size_t)b * 256 + c0) * HW;
    for (int i = tid; i < 128 * 56; i += 256) {
        int cl = i / 56, s = i - 56 * cl;
        int y = wy0 + s / 14, x = s - 14 * (s / 14);
        sm[cl][s] = (y >= 0 && y < 14) ? src[(size_t)cl * HW + y * 14 + x] : 0.f;
    }
    __syncthreads();

    for (int t = wrp; t < 576; t += 8) {
        int nl = t & 15, seg = t >> 4;
        int r = seg / 4, cg = seg & 3;
        int cl = cg * 32 + lane;
        int n = n0 + nl;
        int dy = r / 3 - 1, dx = r - (r / 3) * 3 - 1;
        int y = n / 14 + dy, x = n - 14 * (n / 14) + dx;
        float v = 0.f;
        if (n < HW && y >= 0 && y < 14 && x >= 0 && x < 14)
            v = sm[cl][(y - wy0) * 14 + x];
        bf16 h = __float2bfloat16(v);
        float l = v - __bfloat162float(h);
        size_t o = ((size_t)b * NP + n) * 2304 + r * 256 + c0 + cl;
        dhi[o] = h;
        dlo[o] = __float2bfloat16(l);
    }
}

// ---------------- warp-MMA GEMM: 128m x 112n block tile, bf16 3-term ------------
// 8 warps (4m x 2n); warp tile 32m x 56n = 2 x 7 m16n8k16 tiles.
// A = cw[b][M][K] (row-major, K-major rows), B = xt[b][224][K] (n rows of K
// = col-major B). Smem rows padded to 48B -> ldmatrix conflict-free.
template<bool FUSE>
__global__ void __launch_bounds__(256)
mma_kernel(const bf16* __restrict__ Ahg, const bf16* __restrict__ Alg,
           const bf16* __restrict__ Bhg, const bf16* __restrict__ Blg,
           float* __restrict__ dst,
           const float* __restrict__ gam, const float* __restrict__ bet,
           const float* __restrict__ mu,  const float* __restrict__ var,
           const float* __restrict__ resid,
           int M_total, int K, int Kc)
{
    __shared__ __align__(16) bf16 Ah[2][128][24];
    __shared__ __align__(16) bf16 Al[2][128][24];
    __shared__ __align__(16) bf16 Bh[2][112][24];
    __shared__ __align__(16) bf16 Bl[2][112][24];

    const int b     = blockIdx.z;
    const int split = blockIdx.y >> 1;
    const int nbase = (blockIdx.y & 1) * 112;
    const int mbase = blockIdx.x * 128;
    const int tid   = threadIdx.x;
    const int wid   = tid >> 5, lane = tid & 31;
    const int wm    = (wid & 3) * 32;      // warp m offset in block tile
    const int wn    = (wid >> 2) * 56;     // warp n offset in block tile
    const int kbeg  = split * Kc;
    const int nk    = Kc / 16;

    const bf16* gAh = Ahg + ((size_t)b * M_total + mbase) * K + kbeg;
    const bf16* gAl = Alg + ((size_t)b * M_total + mbase) * K + kbeg;
    const bf16* gBh = Bhg + ((size_t)b * NP + nbase) * K + kbeg;
    const bf16* gBl = Blg + ((size_t)b * NP + nbase) * K + kbeg;

    float acc[2][7][4];
    #pragma unroll
    for (int s = 0; s < 2; s++)
        #pragma unroll
        for (int t = 0; t < 7; t++)
            #pragma unroll
            for (int i = 0; i < 4; i++) acc[s][t][i] = 0.f;

    auto fill = [&](int kt, int buf) {
        const int k0 = kt * 16;
        {
            int row = tid >> 1, ch = tid & 1;
            const size_t go = (size_t)row * K + k0 + ch * 8;
            cp16(&Ah[buf][row][ch * 8], gAh + go);
            cp16(&Al[buf][row][ch * 8], gAl + go);
        }
        if (tid < 224) {
            int row = tid >> 1, ch = tid & 1;
            const size_t go = (size_t)row * K + k0 + ch * 8;
            cp16(&Bh[buf][row][ch * 8], gBh + go);
            cp16(&Bl[buf][row][ch * 8], gBl + go);
        }
    };

    fill(0, 0); CP_COMMIT();

    const int lm = lane & 15, lk = lane >> 4;          // A ldmatrix addressing
    const int ln = lane & 7,  lk2 = (lane >> 3) & 1;   // B ldmatrix addressing

    for (int kt = 0; kt < nk; kt++) {
        const int cur = kt & 1, nxt = cur ^ 1;
        const bool has = (kt + 1 < nk);
        if (has) { fill(kt + 1, nxt); CP_COMMIT(); }
        if (has) asm volatile("cp.async.wait_group 1;" ::: "memory");
        else     asm volatile("cp.async.wait_group 0;" ::: "memory");
        __syncthreads();

        uint32_t ah[2][4], al[2][4];
        #pragma unroll
        for (int s = 0; s < 2; s++) {
            ldsm_x4(ah[s], smem_u32(&Ah[cur][wm + s * 16 + lm][lk * 8]));
            ldsm_x4(al[s], smem_u32(&Al[cur][wm + s * 16 + lm][lk * 8]));
        }
        uint32_t bh[7][2], bl[7][2];
        #pragma unroll
        for (int t = 0; t < 7; t++) {
            ldsm_x2(bh[t], smem_u32(&Bh[cur][wn + t * 8 + ln][lk2 * 8]));
            ldsm_x2(bl[t], smem_u32(&Bl[cur][wn + t * 8 + ln][lk2 * 8]));
        }
        #pragma unroll
        for (int s = 0; s < 2; s++)
            #pragma unroll
            for (int t = 0; t < 7; t++) {
                mma_bf16(acc[s][t], ah[s], bh[t]);
                mma_bf16(acc[s][t], ah[s], bl[t]);
                mma_bf16(acc[s][t], al[s], bh[t]);
            }
        __syncthreads();
    }

    // ---- epilogue ----
    const int tm = lane >> 2, tn2 = (lane & 3) * 2;
    if (FUSE) {
        #pragma unroll
        for (int s = 0; s < 2; s++) {
            int r0 = mbase + wm + s * 16 + tm;
            int r1 = r0 + 8;
            float i0 = rsqrtf(var[r0] + EPS) * gam[r0];
            float b0 = bet[r0] - mu[r0] * i0;
            float i1 = rsqrtf(var[r1] + EPS) * gam[r1];
            float b1 = bet[r1] - mu[r1] * i1;
            size_t o0 = ((size_t)b * M_total + r0) * HW;
            size_t o1 = ((size_t)b * M_total + r1) * HW;
            #pragma unroll
            for (int t = 0; t < 7; t++) {
                int n = nbase + wn + t * 8 + tn2;
                if (n < HW) {
                    float2 v0, v1;
                    v0.x = fmaxf(fmaf(acc[s][t][0], i0, b0) + resid[o0 + n],     0.f);
                    v0.y = fmaxf(fmaf(acc[s][t][1], i0, b0) + resid[o0 + n + 1], 0.f);
                    v1.x = fmaxf(fmaf(acc[s][t][2], i1, b1) + resid[o1 + n],     0.f);
                    v1.y = fmaxf(fmaf(acc[s][t][3], i1, b1) + resid[o1 + n + 1], 0.f);
                    *(float2*)(dst + o0 + n) = v0;
                    *(float2*)(dst + o1 + n) = v1;
                }
            }
        }
    } else {
        #pragma unroll
        for (int s = 0; s < 2; s++) {
            int r0 = mbase + wm + s * 16 + tm;
            size_t o0 = (((size_t)split * BB + b) * M_total + r0) * HW;
            size_t o1 = o0 + 8 * HW;
            #pragma unroll
            for (int t = 0; t < 7; t++) {
                int n = nbase + wn + t * 8 + tn2;
                if (n < HW) {
                    *(float2*)(dst + o0 + n) = make_float2(acc[s][t][0], acc[s][t][1]);
                    *(float2*)(dst + o1 + n) = make_float2(acc[s][t][2], acc[s][t][3]);
                }
            }
        }
    }
}

// ---------------- split-K(2) reduce + BN + ReLU + next-stage pool ----------------
__global__ void reduce_bn_relu_pool(const float* __restrict__ Part, float* __restrict__ Out,
                                    float* __restrict__ Pooled,
                                    const float* __restrict__ gam, const float* __restrict__ bet,
                                    const float* __restrict__ mu,  const float* __restrict__ var,
                                    int rows)
{
    int gid  = blockIdx.x * 4 + (threadIdx.x >> 5);
    int lane = threadIdx.x & 31;
    if (gid >= rows) return;
    int m = gid & 255;
    const size_t stride = (size_t)rows * HW;
    float inv  = rsqrtf(var[m] + EPS) * gam[m];
    float beta = bet[m] - mu[m] * inv;
    size_t base = (size_t)gid * HW;
    float psum = 0.f;
    for (int n = lane; n < HW; n += 32) {
        float s = Part[base + n] + Part[stride + base + n];
        float v = fmaxf(fmaf(s, inv, beta), 0.f);
        Out[base + n] = v;
        psum += v;
    }
    #pragma unroll
    for (int o = 16; o; o >>= 1) psum += __shfl_down_sync(0xffffffffu, psum, o);
    if (lane == 0) Pooled[gid] = psum * (1.0f / HW);
}

// ------------------------------------------------------------------------------
extern "C" void kernel_launch(void* const* d_in, const int* in_sizes, int n_in,
                              void* d_out, int out_size)
{
    const float* x    = (const float*)d_in[0];
    const float* w1   = (const float*)d_in[1];
    const float* w2   = (const float*)d_in[2];
    const float* w3   = (const float*)d_in[3];
    const float* r1w  = (const float*)d_in[4];
    const float* r1b  = (const float*)d_in[5];
    const float* r2w  = (const float*)d_in[6];
    const float* r2b  = (const float*)d_in[7];
    const float* r3w  = (const float*)d_in[8];
    const float* r3b  = (const float*)d_in[9];
    const float* bn1g = (const float*)d_in[10];
    const float* bn1b = (const float*)d_in[11];
    const float* bn1m = (const float*)d_in[12];
    const float* bn1v = (const float*)d_in[13];
    const float* bn2g = (const float*)d_in[14];
    const float* bn2b = (const float*)d_in[15];
    const float* bn2m = (const float*)d_in[16];
    const float* bn2v = (const float*)d_in[17];
    const float* bn3g = (const float*)d_in[18];
    const float* bn3b = (const float*)d_in[19];
    const float* bn3m = (const float*)d_in[20];
    const float* bn3v = (const float*)d_in[21];
    float* out = (float*)d_out;

    float *pooled, *rw, *o1, *o2, *part;
    bf16 *cwh, *cwl, *xth, *xtl;
    cudaGetSymbolAddress((void**)&pooled, g_pooled);
    cudaGetSymbolAddress((void**)&rw,     g_rw);
    cudaGetSymbolAddress((void**)&o1,     g_o1);
    cudaGetSymbolAddress((void**)&o2,     g_o2);
    cudaGetSymbolAddress((void**)&part,   g_part);
    cudaGetSymbolAddress((void**)&cwh,    g_cwh);
    cudaGetSymbolAddress((void**)&cwl,    g_cwl);
    cudaGetSymbolAddress((void**)&xth,    g_xth);
    cudaGetSymbolAddress((void**)&xtl,    g_xtl);

    const int ROWS = BB * 256;

    // ---- stage 1: 1x1, K=1024 -> M=256, split-K=2 ----
    pool_kernel<<<(BB * 1024 * 32 + 255) / 256, 256>>>(x, pooled, BB * 1024);
    route_kernel<<<BB, 256>>>(pooled, r1w, r1b, rw, 1024);
    combine_bf16_kernel<<<256, 256>>>(w1, rw, cwh, cwl, 256 * 1024);
    transpose_kernel<<<dim3(1024 / 32, 7, BB), dim3(32, 8)>>>(x, xth, xtl, 1024);
    mma_kernel<false><<<dim3(2, 4, BB), 256>>>(
        cwh, cwl, xth, xtl, part, nullptr, nullptr, nullptr, nullptr, nullptr,
        256, 1024, 512);
    reduce_bn_relu_pool<<<ROWS / 4, 128>>>(part, o1, pooled, bn1g, bn1b, bn1m, bn1v, ROWS);

    // ---- stage 2: 3x3 (k = r*256+c), K=2304 -> M=256, split-K=2 ----
    route_kernel<<<BB, 256>>>(pooled, r2w, r2b, rw, 256);
    combine2_kernel<<<256, 256>>>(w2, rw, cwh, cwl);
    xt2_kernel<<<dim3(14, 2, BB), 256>>>(o1, xth, xtl);
    mma_kernel<false><<<dim3(2, 4, BB), 256>>>(
        cwh, cwl, xth, xtl, part, nullptr, nullptr, nullptr, nullptr, nullptr,
        256, 2304, 1152);
    reduce_bn_relu_pool<<<ROWS / 4, 128>>>(part, o2, pooled, bn2g, bn2b, bn2m, bn2v, ROWS);

    // ---- stage 3: 1x1, K=256 -> M=1024, fused BN+resid+ReLU ----
    route_kernel<<<BB, 256>>>(pooled, r3w, r3b, rw, 256);
    combine_bf16_kernel<<<256, 256>>>(w3, rw, cwh, cwl, 1024 * 256);
    transpose_kernel<<<dim3(256 / 32, 7, BB), dim3(32, 8)>>>(o2, xth, xtl, 256);
    mma_kernel<true><<<dim3(8, 2, BB), 256>>>(
        cwh, cwl, xth, xtl, out, bn3g, bn3b, bn3m, bn3v, x,
        1024, 256, 256);
}